// round 3
// baseline (speedup 1.0000x reference)
#include <cuda_runtime.h>
#include <cstdint>

// Problem constants (fixed shapes)
#define BATCH      64
#define CHN        256
#define HH         64
#define WW         64
#define HW         (HH * WW)            // 4096
#define CHW        (CHN * HW)           // 1048576 elements per batch
#define KTOP       8
#define OUT_ROW    (CHN + 3)            // 259
#define BLOCKS_PB  64                   // phase-1 blocks per batch
#define THREADS    256
#define F4_PER_B   (CHW / 4)            // 262144 float4 per batch
#define F4_STRIDE  (BLOCKS_PB * THREADS)// 16384
#define F4_ITERS   (F4_PER_B / F4_STRIDE) // 16

// Scratch: per (batch, block) top-8 packed candidates. 64*64*8 u64 = 256 KB.
__device__ unsigned long long g_partial[BATCH * BLOCKS_PB * KTOP];

// Pack (value, index) so that u64 max-order == (value desc, index asc).
// Values are uniform in [0,1) -> non-negative floats, so the raw bit pattern
// is monotone in value. Complement the index so a LOWER index packs LARGER,
// matching lax.top_k's stable tie-break.
__device__ __forceinline__ unsigned long long pack_vi(unsigned vbits, unsigned idx) {
    return ((unsigned long long)vbits << 32) | (unsigned long long)(0xFFFFFFFFu - idx);
}

// Insert packed candidate into a sorted-descending 8-list (rare path).
__device__ __forceinline__ void insert8(unsigned long long (&top)[KTOP], unsigned long long pk) {
    top[KTOP - 1] = pk;
#pragma unroll
    for (int j = KTOP - 1; j > 0; j--) {
        unsigned long long a = top[j - 1], b = top[j];
        if (b > a) { top[j - 1] = b; top[j] = a; }
    }
}

// Block-wide top-8 of the union of per-thread sorted lists (length <= L each),
// via 8 rounds of shared-mem u64 atomicMax. Results land in s_res[0..7],
// sorted descending.
template <int L>
__device__ __forceinline__ void block_top8(const unsigned long long (&mine)[L],
                                           unsigned long long* s_res,
                                           unsigned long long* s_best) {
    int p = 0;
    for (int r = 0; r < KTOP; r++) {
        if (threadIdx.x == 0) *s_best = 0ULL;
        __syncthreads();
        unsigned long long c = (p < L) ? mine[p] : 0ULL;
        if (c) atomicMax(s_best, c);
        __syncthreads();
        unsigned long long bst = *s_best;
        if (c != 0ULL && c == bst) p++;   // packed values are unique (unique indices)
        if (threadIdx.x == 0) s_res[r] = bst;
        __syncthreads();                  // protect s_best read vs next-round reset
    }
}

// ---------------------------------------------------------------------------
// Phase 1: stream 256 MB, per-block top-8 -> g_partial
// ---------------------------------------------------------------------------
__global__ __launch_bounds__(THREADS)
void topk_phase1(const float* __restrict__ x) {
    const int b   = blockIdx.y;
    const int blk = blockIdx.x;
    const int tid = threadIdx.x;

    const float4* __restrict__ xb = (const float4*)(x + (size_t)b * CHW);

    unsigned long long top[KTOP];
#pragma unroll
    for (int i = 0; i < KTOP; i++) top[i] = 0ULL;
    unsigned min_hi = 0;  // high 32 bits (value bits) of top[7], fast reject

    const int base4 = blk * THREADS + tid;
#pragma unroll
    for (int i = 0; i < F4_ITERS; i++) {
        const int f4 = base4 + i * F4_STRIDE;
        const float4 v = xb[f4];
        const unsigned idx0 = (unsigned)f4 * 4u;

        const unsigned b0 = __float_as_uint(v.x);
        const unsigned b1 = __float_as_uint(v.y);
        const unsigned b2 = __float_as_uint(v.z);
        const unsigned b3 = __float_as_uint(v.w);

        // Fast path: single u32 compare per element; insertion is rare.
        if (b0 >= min_hi) {
            unsigned long long pk = pack_vi(b0, idx0 + 0);
            if (pk > top[KTOP - 1]) { insert8(top, pk); min_hi = (unsigned)(top[KTOP - 1] >> 32); }
        }
        if (b1 >= min_hi) {
            unsigned long long pk = pack_vi(b1, idx0 + 1);
            if (pk > top[KTOP - 1]) { insert8(top, pk); min_hi = (unsigned)(top[KTOP - 1] >> 32); }
        }
        if (b2 >= min_hi) {
            unsigned long long pk = pack_vi(b2, idx0 + 2);
            if (pk > top[KTOP - 1]) { insert8(top, pk); min_hi = (unsigned)(top[KTOP - 1] >> 32); }
        }
        if (b3 >= min_hi) {
            unsigned long long pk = pack_vi(b3, idx0 + 3);
            if (pk > top[KTOP - 1]) { insert8(top, pk); min_hi = (unsigned)(top[KTOP - 1] >> 32); }
        }
    }

    __shared__ unsigned long long s_best;
    __shared__ unsigned long long s_res[KTOP];
    block_top8<KTOP>(top, s_res, &s_best);

    if (tid < KTOP)
        g_partial[(b * BLOCKS_PB + blk) * KTOP + tid] = s_res[tid];
}

// ---------------------------------------------------------------------------
// Phase 2: per batch, reduce 512 candidates -> final top-8, emit output row
// ---------------------------------------------------------------------------
__global__ __launch_bounds__(THREADS)
void topk_phase2(float* __restrict__ out) {
    const int b   = blockIdx.x;
    const int tid = threadIdx.x;

    // Each thread grabs 2 of the 512 candidates, kept sorted descending.
    const unsigned long long* src = &g_partial[b * BLOCKS_PB * KTOP];
    unsigned long long mine[2];
    {
        unsigned long long a = src[tid];
        unsigned long long c = src[tid + THREADS];
        mine[0] = a > c ? a : c;
        mine[1] = a > c ? c : a;
    }

    __shared__ unsigned long long s_best;
    __shared__ unsigned long long s_res[KTOP];
    block_top8<2>(mine, s_res, &s_best);

    float* __restrict__ rowb = out + (size_t)b * KTOP * OUT_ROW;

    // Zero the whole [8, 259] slab (d_out is poisoned).
    for (int i = tid; i < KTOP * OUT_ROW; i += THREADS) rowb[i] = 0.0f;
    __syncthreads();

    if (tid < KTOP) {
        const unsigned long long pk = s_res[tid];
        const float    val = __uint_as_float((unsigned)(pk >> 32));
        const unsigned idx = 0xFFFFFFFFu - (unsigned)(pk & 0xFFFFFFFFull);
        const unsigned ch  = idx >> 12;          // / 4096
        const unsigned rem = idx & 4095u;
        const float yn = (float)(rem >> 6)  * (1.0f / 63.0f);
        const float xn = (float)(rem & 63u) * (1.0f / 63.0f);
        float* row = rowb + tid * OUT_ROW;
        row[ch]       = 1.0f;
        row[CHN]      = val;
        row[CHN + 1]  = xn;
        row[CHN + 2]  = yn;
    }
}

extern "C" void kernel_launch(void* const* d_in, const int* in_sizes, int n_in,
                              void* d_out, int out_size) {
    (void)in_sizes; (void)n_in; (void)out_size;
    const float* x = (const float*)d_in[0];
    float* out = (float*)d_out;

    dim3 g1(BLOCKS_PB, BATCH);
    topk_phase1<<<g1, THREADS>>>(x);
    topk_phase2<<<BATCH, THREADS>>>(out);
}

// round 4
// speedup vs baseline: 2.0710x; 2.0710x over previous
#include <cuda_runtime.h>
#include <cstdint>

// Problem constants (fixed shapes)
#define BATCH      64
#define CHN        256
#define HH         64
#define WW         64
#define HW         (HH * WW)            // 4096
#define CHW        (CHN * HW)           // 1048576 elements per batch
#define KTOP       8
#define OUT_ROW    (CHN + 3)            // 259
#define BLOCKS_PB  8                    // phase-1 blocks per batch
#define THREADS    256
#define F4_PER_B   (CHW / 4)            // 262144 float4 per batch
#define F4_STRIDE  (BLOCKS_PB * THREADS)      // 2048
#define F4_ITERS   (F4_PER_B / F4_STRIDE)     // 128
#define UNROLL     8

// Scratch: per (batch, block) top-8 packed candidates. 64*8*8 u64 = 32 KB.
__device__ unsigned long long g_partial[BATCH * BLOCKS_PB * KTOP];

// Pack (value, index): u64 max-order == (value desc, index asc).
// Values are uniform [0,1) -> non-negative floats, bit pattern monotone in value.
// Complement index so lower index packs larger (lax.top_k stable tie-break).
__device__ __forceinline__ unsigned long long pack_vi(unsigned vbits, unsigned idx) {
    return ((unsigned long long)vbits << 32) | (unsigned long long)(0xFFFFFFFFu - idx);
}

// Insert packed candidate into sorted-descending 8-list (rare path).
__device__ __forceinline__ void insert8(unsigned long long (&top)[KTOP], unsigned long long pk) {
    top[KTOP - 1] = pk;
#pragma unroll
    for (int j = KTOP - 1; j > 0; j--) {
        unsigned long long a = top[j - 1], b = top[j];
        if (b > a) { top[j - 1] = b; top[j] = a; }
    }
}

// Block-wide top-8 of the union of per-thread sorted lists (length <= L each),
// via 8 rounds of shared-mem u64 atomicMax. s_res[0..7] sorted descending.
template <int L>
__device__ __forceinline__ void block_top8(const unsigned long long (&mine)[L],
                                           unsigned long long* s_res,
                                           unsigned long long* s_best) {
    int p = 0;
    for (int r = 0; r < KTOP; r++) {
        if (threadIdx.x == 0) *s_best = 0ULL;
        __syncthreads();
        unsigned long long c = (p < L) ? mine[p] : 0ULL;
        if (c) atomicMax(s_best, c);
        __syncthreads();
        unsigned long long bst = *s_best;
        if (c != 0ULL && c == bst) p++;   // packed values unique (distinct indices)
        if (threadIdx.x == 0) s_res[r] = bst;
        __syncthreads();
    }
}

// ---------------------------------------------------------------------------
// Phase 1: stream 256 MB, per-block top-8 -> g_partial.
// Shared threshold sT = max over threads of (that thread's 8th-best value bits).
// Valid reject bound: if v < sT then >=8 block values beat v.
// ---------------------------------------------------------------------------
__global__ __launch_bounds__(THREADS)
void topk_phase1(const float* __restrict__ x) {
    const int b   = blockIdx.y;
    const int blk = blockIdx.x;
    const int tid = threadIdx.x;

    const float4* __restrict__ xb = (const float4*)(x + (size_t)b * CHW);

    __shared__ unsigned sT;
    if (tid == 0) sT = 0u;
    __syncthreads();

    unsigned long long top[KTOP];
#pragma unroll
    for (int i = 0; i < KTOP; i++) top[i] = 0ULL;
    unsigned min_hi = 0;   // value bits of local 8th best
    unsigned thr    = 0;   // max(min_hi, sT), refreshed per outer iter

    const int base4 = blk * THREADS + tid;

#pragma unroll 1
    for (int i = 0; i < F4_ITERS; i += UNROLL) {
        // Refresh threshold from shared (stale is safe: only affects filtering strength).
        unsigned st = *(volatile unsigned*)&sT;
        thr = (min_hi > st) ? min_hi : st;

#pragma unroll
        for (int u = 0; u < UNROLL; u++) {
            const int f4 = base4 + (i + u) * F4_STRIDE;
            const float4 v = xb[f4];
            const unsigned idx0 = (unsigned)f4 * 4u;

            const unsigned c0 = __float_as_uint(v.x);
            const unsigned c1 = __float_as_uint(v.y);
            const unsigned c2 = __float_as_uint(v.z);
            const unsigned c3 = __float_as_uint(v.w);

#define TRY_CAND(bits, off)                                                      \
            if ((bits) >= thr) {                                                 \
                unsigned long long pk = pack_vi((bits), idx0 + (off));           \
                if (pk > top[KTOP - 1]) {                                        \
                    insert8(top, pk);                                            \
                    min_hi = (unsigned)(top[KTOP - 1] >> 32);                    \
                    if (min_hi > thr) thr = min_hi;                              \
                    atomicMax(&sT, min_hi);                                      \
                }                                                                \
            }
            TRY_CAND(c0, 0)
            TRY_CAND(c1, 1)
            TRY_CAND(c2, 2)
            TRY_CAND(c3, 3)
#undef TRY_CAND
        }
    }

    __shared__ unsigned long long s_best;
    __shared__ unsigned long long s_res[KTOP];
    block_top8<KTOP>(top, s_res, &s_best);

    if (tid < KTOP)
        g_partial[(b * BLOCKS_PB + blk) * KTOP + tid] = s_res[tid];
}

// ---------------------------------------------------------------------------
// Phase 2: per batch, reduce 64 candidates -> final top-8, emit output row.
// ---------------------------------------------------------------------------
__global__ __launch_bounds__(THREADS)
void topk_phase2(float* __restrict__ out) {
    const int b   = blockIdx.x;
    const int tid = threadIdx.x;

    const unsigned long long* src = &g_partial[b * BLOCKS_PB * KTOP];
    unsigned long long mine[1];
    mine[0] = (tid < BLOCKS_PB * KTOP) ? src[tid] : 0ULL;

    __shared__ unsigned long long s_best;
    __shared__ unsigned long long s_res[KTOP];
    block_top8<1>(mine, s_res, &s_best);

    float* __restrict__ rowb = out + (size_t)b * KTOP * OUT_ROW;

    // Zero the whole [8, 259] slab (d_out is poisoned).
    for (int i = tid; i < KTOP * OUT_ROW; i += THREADS) rowb[i] = 0.0f;
    __syncthreads();

    if (tid < KTOP) {
        const unsigned long long pk = s_res[tid];
        const float    val = __uint_as_float((unsigned)(pk >> 32));
        const unsigned idx = 0xFFFFFFFFu - (unsigned)(pk & 0xFFFFFFFFull);
        const unsigned ch  = idx >> 12;          // / 4096
        const unsigned rem = idx & 4095u;
        const float yn = (float)(rem >> 6)  * (1.0f / 63.0f);
        const float xn = (float)(rem & 63u) * (1.0f / 63.0f);
        float* row = rowb + tid * OUT_ROW;
        row[ch]       = 1.0f;
        row[CHN]      = val;
        row[CHN + 1]  = xn;
        row[CHN + 2]  = yn;
    }
}

extern "C" void kernel_launch(void* const* d_in, const int* in_sizes, int n_in,
                              void* d_out, int out_size) {
    (void)in_sizes; (void)n_in; (void)out_size;
    const float* x = (const float*)d_in[0];
    float* out = (float*)d_out;

    dim3 g1(BLOCKS_PB, BATCH);
    topk_phase1<<<g1, THREADS>>>(x);
    topk_phase2<<<BATCH, THREADS>>>(out);
}